// round 1
// baseline (speedup 1.0000x reference)
#include <cuda_runtime.h>
#include <cuda_bf16.h>
#include <math.h>

// Problem constants (fixed by the dataset)
#define BB 32
#define CC 512
#define NN 1024   // H*W = 32*32
#define RR 64
#define EPS 1e-5f
#define SCALE 0.04419417382415922f   // C^-0.5 = 1/sqrt(512)

// Scratch: t, p, g, y each [B, N, R] fp32 (p stored transposed as [b, m, r])
__device__ float d_t[BB * NN * RR];
__device__ float d_p[BB * NN * RR];
__device__ float d_g[BB * NN * RR];
__device__ float d_y[BB * NN * RR];

// ---------------------------------------------------------------------------
// Kernel 1: projections.  out[b, n, r] = sum_c x[b, c, n] * W[r, c] + bias[r]
// GEMM: M = B*N (rows, A[row, c] = x with stride N over c), K = C, Ncols = R.
// Tile 128(n) x 64(r), BK=16, 128 threads, 8x8 microtile (split octets).
// ---------------------------------------------------------------------------
__global__ __launch_bounds__(128) void proj_kernel(
    const float* __restrict__ x,
    const float* __restrict__ Wt, const float* __restrict__ bt,
    const float* __restrict__ Wp, const float* __restrict__ bp,
    const float* __restrict__ Wg, const float* __restrict__ bg)
{
    const int which = blockIdx.z;
    const float* W    = (which == 0) ? Wt : (which == 1) ? Wp : Wg;
    const float* bias = (which == 0) ? bt : (which == 1) ? bp : bg;
    float* out        = (which == 0) ? d_t : (which == 1) ? d_p : d_g;

    const int tile = blockIdx.x;        // 0..255 (32768 rows / 128)
    const int b    = tile >> 3;         // 8 tiles per batch (1024/128)
    const int n0   = (tile & 7) << 7;   // *128
    const int tid  = threadIdx.x;
    const int tx   = tid & 7;           // col octet: tx*4..+3 and 32+tx*4..+3
    const int ty   = tid >> 3;          // row octet: ty*4..+3 and 64+ty*4..+3

    __shared__ float As[16][132];  // [k][n]
    __shared__ float Bs[16][68];   // [k][r]

    float acc[8][8];
#pragma unroll
    for (int i = 0; i < 8; i++)
#pragma unroll
        for (int j = 0; j < 8; j++) acc[i][j] = 0.f;

    const float* xb = x + (size_t)b * CC * NN + n0;

    for (int k0 = 0; k0 < CC; k0 += 16) {
        // Load A tile: 16 c-rows x 128 n (512 float4), coalesced.
#pragma unroll
        for (int p4 = 0; p4 < 4; p4++) {
            int idx = p4 * 128 + tid;
            int c_l = idx >> 5;
            int n4  = idx & 31;
            float4 v = *reinterpret_cast<const float4*>(xb + (size_t)(k0 + c_l) * NN + n4 * 4);
            *reinterpret_cast<float4*>(&As[c_l][n4 * 4]) = v;
        }
        // Load B tile transposed: W[r, c] -> Bs[c][r] (256 float4 reads).
#pragma unroll
        for (int p4 = 0; p4 < 2; p4++) {
            int idx = p4 * 128 + tid;
            int r_l = idx >> 2;
            int c4  = idx & 3;
            float4 v = *reinterpret_cast<const float4*>(W + (size_t)r_l * CC + k0 + c4 * 4);
            Bs[c4 * 4 + 0][r_l] = v.x;
            Bs[c4 * 4 + 1][r_l] = v.y;
            Bs[c4 * 4 + 2][r_l] = v.z;
            Bs[c4 * 4 + 3][r_l] = v.w;
        }
        __syncthreads();
#pragma unroll
        for (int k = 0; k < 16; k++) {
            float4 a0 = *reinterpret_cast<float4*>(&As[k][ty * 4]);
            float4 a1 = *reinterpret_cast<float4*>(&As[k][64 + ty * 4]);
            float4 b0 = *reinterpret_cast<float4*>(&Bs[k][tx * 4]);
            float4 b1 = *reinterpret_cast<float4*>(&Bs[k][32 + tx * 4]);
            float av[8] = {a0.x, a0.y, a0.z, a0.w, a1.x, a1.y, a1.z, a1.w};
            float bv[8] = {b0.x, b0.y, b0.z, b0.w, b1.x, b1.y, b1.z, b1.w};
#pragma unroll
            for (int i = 0; i < 8; i++)
#pragma unroll
                for (int j = 0; j < 8; j++) acc[i][j] += av[i] * bv[j];
        }
        __syncthreads();
    }

    // Epilogue: add bias, write [b, n, r].
    float bvr[8];
#pragma unroll
    for (int j = 0; j < 4; j++) {
        bvr[j]     = bias[tx * 4 + j];
        bvr[4 + j] = bias[32 + tx * 4 + j];
    }
    float* ob = out + ((size_t)b * NN + n0) * RR;
#pragma unroll
    for (int i = 0; i < 8; i++) {
        int n = (i < 4) ? (ty * 4 + i) : (64 + ty * 4 + (i - 4));
#pragma unroll
        for (int h = 0; h < 2; h++) {
            float4 v;
            v.x = acc[i][h * 4 + 0] + bvr[h * 4 + 0];
            v.y = acc[i][h * 4 + 1] + bvr[h * 4 + 1];
            v.z = acc[i][h * 4 + 2] + bvr[h * 4 + 2];
            v.w = acc[i][h * 4 + 3] + bvr[h * 4 + 3];
            int r = (h == 0) ? (tx * 4) : (32 + tx * 4);
            *reinterpret_cast<float4*>(ob + (size_t)n * RR + r) = v;
        }
    }
}

// ---------------------------------------------------------------------------
// Kernel 2: attention with online softmax.
// Per block: batch b, 32 n-rows. Loop m-chunks of 64.
//   phase1: S[m][n] = scale * sum_r t[n,r] p[m,r]   (2n x 4m microtile)
//   phase2: online softmax over m (8-lane shfl groups per n row)
//   phase3: y[n,r] += w[m,n] * g[m,r]               (4n x 2r microtile)
// ---------------------------------------------------------------------------
__global__ __launch_bounds__(256) void attn_kernel()
{
    const int b  = blockIdx.y;
    const int n0 = blockIdx.x * 32;
    const int tid = threadIdx.x;

    __shared__ float tS[64][34];    // [r][n]
    __shared__ float buf[64][68];   // p chunk as [r][m]; then g chunk as [m][r]
    __shared__ float wS[64][36];    // scores/weights [m][n]
    __shared__ float fac_s[32];
    __shared__ float rsum_s[32];

    // Load t tile transposed: [n][r] -> tS[r][n]
    const float* tb = d_t + ((size_t)b * NN + n0) * RR;
    for (int i = tid; i < 512; i += 256) {           // 512 float4
        int n  = i >> 4;
        int r4 = (i & 15) * 4;
        float4 v = *reinterpret_cast<const float4*>(tb + (size_t)n * RR + r4);
        tS[r4 + 0][n] = v.x;
        tS[r4 + 1][n] = v.y;
        tS[r4 + 2][n] = v.z;
        tS[r4 + 3][n] = v.w;
    }

    // phase-1 mapping
    const int tx1 = tid & 15;   // m quad: tx1*4..+3
    const int ty1 = tid >> 4;   // n pair: ty1*2, ty1*2+1
    // phase-2 mapping
    const int n2 = tid >> 3;    // n row 0..31
    const int l8 = tid & 7;     // 8-lane group, handles m = l8 + 8k
    // phase-3 mapping
    const int tx3 = tid & 31;   // r pair: tx3*2
    const int ty3 = tid >> 5;   // n quad: ty3*4..+3

    float run_max = -1e30f, run_sum = 0.f;
    float yacc[4][2];
#pragma unroll
    for (int i = 0; i < 4; i++) { yacc[i][0] = 0.f; yacc[i][1] = 0.f; }

    const float* pb = d_p + (size_t)b * NN * RR;
    const float* gb = d_g + (size_t)b * NN * RR;

    __syncthreads();

    for (int m0 = 0; m0 < NN; m0 += 64) {
        // ---- Load p chunk transposed: [m][r] -> buf[r][m]
        for (int i = tid; i < 1024; i += 256) {      // 1024 float4 (64m x 16)
            int m  = i >> 4;
            int r4 = (i & 15) * 4;
            float4 v = *reinterpret_cast<const float4*>(pb + (size_t)(m0 + m) * RR + r4);
            buf[r4 + 0][m] = v.x;
            buf[r4 + 1][m] = v.y;
            buf[r4 + 2][m] = v.z;
            buf[r4 + 3][m] = v.w;
        }
        __syncthreads();

        // ---- Phase 1: scores (2n x 4m per thread)
        {
            float s[2][4];
#pragma unroll
            for (int i = 0; i < 2; i++)
#pragma unroll
                for (int j = 0; j < 4; j++) s[i][j] = 0.f;
#pragma unroll 16
            for (int r = 0; r < 64; r++) {
                float2 tv = *reinterpret_cast<float2*>(&tS[r][ty1 * 2]);
                float4 pv = *reinterpret_cast<float4*>(&buf[r][tx1 * 4]);
                s[0][0] += tv.x * pv.x; s[0][1] += tv.x * pv.y;
                s[0][2] += tv.x * pv.z; s[0][3] += tv.x * pv.w;
                s[1][0] += tv.y * pv.x; s[1][1] += tv.y * pv.y;
                s[1][2] += tv.y * pv.z; s[1][3] += tv.y * pv.w;
            }
#pragma unroll
            for (int j = 0; j < 4; j++) {
                wS[tx1 * 4 + j][ty1 * 2 + 0] = s[0][j] * SCALE;
                wS[tx1 * 4 + j][ty1 * 2 + 1] = s[1][j] * SCALE;
            }
        }
        __syncthreads();

        // ---- Load g chunk (direct, [m][r]) into buf  +  Phase 2 softmax
        for (int i = tid; i < 1024; i += 256) {
            int m  = i >> 4;
            int r4 = (i & 15) * 4;
            *reinterpret_cast<float4*>(&buf[m][r4]) =
                *reinterpret_cast<const float4*>(gb + (size_t)(m0 + m) * RR + r4);
        }
        {
            float sv[8];
#pragma unroll
            for (int k = 0; k < 8; k++) sv[k] = wS[l8 + 8 * k][n2];
            float mx = sv[0];
#pragma unroll
            for (int k = 1; k < 8; k++) mx = fmaxf(mx, sv[k]);
#pragma unroll
            for (int off = 4; off > 0; off >>= 1)
                mx = fmaxf(mx, __shfl_xor_sync(0xffffffffu, mx, off));
            float nmax = fmaxf(run_max, mx);
            float f    = __expf(run_max - nmax);
            float lsum = 0.f;
#pragma unroll
            for (int k = 0; k < 8; k++) {
                sv[k] = __expf(sv[k] - nmax);
                lsum += sv[k];
            }
#pragma unroll
            for (int off = 4; off > 0; off >>= 1)
                lsum += __shfl_xor_sync(0xffffffffu, lsum, off);
            run_sum = run_sum * f + lsum;
            run_max = nmax;
#pragma unroll
            for (int k = 0; k < 8; k++) wS[l8 + 8 * k][n2] = sv[k];
            if (l8 == 0) { fac_s[n2] = f; rsum_s[n2] = run_sum; }
        }
        __syncthreads();

        // ---- Phase 3: y update (4n x 2r per thread)
        {
#pragma unroll
            for (int i = 0; i < 4; i++) {
                float f = fac_s[ty3 * 4 + i];
                yacc[i][0] *= f;
                yacc[i][1] *= f;
            }
#pragma unroll 8
            for (int m = 0; m < 64; m++) {
                float4 wv = *reinterpret_cast<float4*>(&wS[m][ty3 * 4]);
                float2 gv = *reinterpret_cast<float2*>(&buf[m][tx3 * 2]);
                yacc[0][0] += wv.x * gv.x; yacc[0][1] += wv.x * gv.y;
                yacc[1][0] += wv.y * gv.x; yacc[1][1] += wv.y * gv.y;
                yacc[2][0] += wv.z * gv.x; yacc[2][1] += wv.z * gv.y;
                yacc[3][0] += wv.w * gv.x; yacc[3][1] += wv.w * gv.y;
            }
        }
        __syncthreads();
    }

    // Write y = acc / run_sum
    float* yb = d_y + ((size_t)b * NN + n0) * RR;
#pragma unroll
    for (int i = 0; i < 4; i++) {
        float inv = 1.f / rsum_s[ty3 * 4 + i];
        float2 v;
        v.x = yacc[i][0] * inv;
        v.y = yacc[i][1] * inv;
        *reinterpret_cast<float2*>(yb + (size_t)(ty3 * 4 + i) * RR + tx3 * 2) = v;
    }
}

// ---------------------------------------------------------------------------
// Kernel 3: z = y @ Wz^T + bz, then BN(inference) + residual.
// out[b,c,n] = (sum_r y[b,n,r] Wz[c,r] + bz[c] - mean[c]) * rsqrt(var+eps)
//              * gamma[c] + beta[c] + x[b,c,n]
// Tile 64c x 64n, K=64 single stage, 256 threads, 4x4 microtile.
// ---------------------------------------------------------------------------
__global__ __launch_bounds__(256) void out_kernel(
    const float* __restrict__ x,
    const float* __restrict__ Wz, const float* __restrict__ bz,
    const float* __restrict__ gamma, const float* __restrict__ beta,
    const float* __restrict__ bn_mean, const float* __restrict__ bn_var,
    float* __restrict__ out)
{
    const int b  = blockIdx.z;
    const int c0 = blockIdx.y * 64;
    const int n0 = blockIdx.x * 64;
    const int tid = threadIdx.x;
    const int tx = tid & 15;   // n quad
    const int ty = tid >> 4;   // c quad

    __shared__ float yS[64][68];   // [r][n]
    __shared__ float wzS[64][68];  // [r][c]

    const float* yb = d_y + ((size_t)b * NN + n0) * RR;
    for (int i = tid; i < 1024; i += 256) {
        int n  = i >> 4;
        int r4 = (i & 15) * 4;
        float4 v = *reinterpret_cast<const float4*>(yb + (size_t)n * RR + r4);
        yS[r4 + 0][n] = v.x;
        yS[r4 + 1][n] = v.y;
        yS[r4 + 2][n] = v.z;
        yS[r4 + 3][n] = v.w;
    }
    for (int i = tid; i < 1024; i += 256) {
        int c  = i >> 4;
        int r4 = (i & 15) * 4;
        float4 v = *reinterpret_cast<const float4*>(Wz + (size_t)(c0 + c) * RR + r4);
        wzS[r4 + 0][c] = v.x;
        wzS[r4 + 1][c] = v.y;
        wzS[r4 + 2][c] = v.z;
        wzS[r4 + 3][c] = v.w;
    }
    __syncthreads();

    float acc[4][4];
#pragma unroll
    for (int i = 0; i < 4; i++)
#pragma unroll
        for (int j = 0; j < 4; j++) acc[i][j] = 0.f;

#pragma unroll 16
    for (int r = 0; r < 64; r++) {
        float4 cv = *reinterpret_cast<float4*>(&wzS[r][ty * 4]);
        float4 nv = *reinterpret_cast<float4*>(&yS[r][tx * 4]);
        acc[0][0] += cv.x * nv.x; acc[0][1] += cv.x * nv.y; acc[0][2] += cv.x * nv.z; acc[0][3] += cv.x * nv.w;
        acc[1][0] += cv.y * nv.x; acc[1][1] += cv.y * nv.y; acc[1][2] += cv.y * nv.z; acc[1][3] += cv.y * nv.w;
        acc[2][0] += cv.z * nv.x; acc[2][1] += cv.z * nv.y; acc[2][2] += cv.z * nv.z; acc[2][3] += cv.z * nv.w;
        acc[3][0] += cv.w * nv.x; acc[3][1] += cv.w * nv.y; acc[3][2] += cv.w * nv.z; acc[3][3] += cv.w * nv.w;
    }

    // Epilogue
#pragma unroll
    for (int i = 0; i < 4; i++) {
        int c = c0 + ty * 4 + i;
        float a   = rsqrtf(bn_var[c] + EPS) * gamma[c];
        float off = (bz[c] - bn_mean[c]) * a + beta[c];
        size_t base = (size_t)b * CC * NN + (size_t)c * NN + n0 + tx * 4;
        float4 xv = *reinterpret_cast<const float4*>(x + base);
        float4 o;
        o.x = acc[i][0] * a + off + xv.x;
        o.y = acc[i][1] * a + off + xv.y;
        o.z = acc[i][2] * a + off + xv.z;
        o.w = acc[i][3] * a + off + xv.w;
        *reinterpret_cast<float4*>(out + base) = o;
    }
}

// ---------------------------------------------------------------------------
extern "C" void kernel_launch(void* const* d_in, const int* in_sizes, int n_in,
                              void* d_out, int out_size)
{
    (void)in_sizes; (void)n_in; (void)out_size;
    const float* x       = (const float*)d_in[0];
    const float* Wt      = (const float*)d_in[1];
    const float* bt      = (const float*)d_in[2];
    const float* Wp      = (const float*)d_in[3];
    const float* bp      = (const float*)d_in[4];
    const float* Wg      = (const float*)d_in[5];
    const float* bg      = (const float*)d_in[6];
    const float* Wz      = (const float*)d_in[7];
    const float* bz      = (const float*)d_in[8];
    const float* gamma   = (const float*)d_in[9];
    const float* beta    = (const float*)d_in[10];
    const float* bn_mean = (const float*)d_in[11];
    const float* bn_var  = (const float*)d_in[12];
    float* out = (float*)d_out;

    proj_kernel<<<dim3(256, 1, 3), 128>>>(x, Wt, bt, Wp, bp, Wg, bg);
    attn_kernel<<<dim3(32, 32), 256>>>();
    out_kernel<<<dim3(16, 8, 32), 256>>>(x, Wz, bz, gamma, beta, bn_mean, bn_var, out);
}

// round 2
// speedup vs baseline: 1.0011x; 1.0011x over previous
#include <cuda_runtime.h>
#include <cuda_bf16.h>
#include <math.h>

// Problem constants (fixed by the dataset)
#define BB 32
#define CC 512
#define NN 1024   // H*W = 32*32
#define RR 64
#define EPS 1e-5f
#define SCALE 0.04419417382415922f   // C^-0.5 = 1/sqrt(512)

// Scratch: t, p, g, y each [B, N, R] fp32 (p stored transposed as [b, m, r])
__device__ float d_t[BB * NN * RR];
__device__ float d_p[BB * NN * RR];
__device__ float d_g[BB * NN * RR];
__device__ float d_y[BB * NN * RR];

// ---------------------------------------------------------------------------
// Kernel 1: projections.  out[b, n, r] = sum_c x[b, c, n] * W[r, c] + bias[r]
// GEMM: M = B*N (rows, A[row, c] = x with stride N over c), K = C, Ncols = R.
// Tile 128(n) x 64(r), BK=16, 128 threads, 8x8 microtile (split octets).
// ---------------------------------------------------------------------------
__global__ __launch_bounds__(128) void proj_kernel(
    const float* __restrict__ x,
    const float* __restrict__ Wt, const float* __restrict__ bt,
    const float* __restrict__ Wp, const float* __restrict__ bp,
    const float* __restrict__ Wg, const float* __restrict__ bg)
{
    const int which = blockIdx.z;
    const float* W    = (which == 0) ? Wt : (which == 1) ? Wp : Wg;
    const float* bias = (which == 0) ? bt : (which == 1) ? bp : bg;
    float* out        = (which == 0) ? d_t : (which == 1) ? d_p : d_g;

    const int tile = blockIdx.x;        // 0..255 (32768 rows / 128)
    const int b    = tile >> 3;         // 8 tiles per batch (1024/128)
    const int n0   = (tile & 7) << 7;   // *128
    const int tid  = threadIdx.x;
    const int tx   = tid & 7;           // col octet: tx*4..+3 and 32+tx*4..+3
    const int ty   = tid >> 3;          // row octet: ty*4..+3 and 64+ty*4..+3

    __shared__ float As[16][132];  // [k][n]
    __shared__ float Bs[16][68];   // [k][r]

    float acc[8][8];
#pragma unroll
    for (int i = 0; i < 8; i++)
#pragma unroll
        for (int j = 0; j < 8; j++) acc[i][j] = 0.f;

    const float* xb = x + (size_t)b * CC * NN + n0;

    for (int k0 = 0; k0 < CC; k0 += 16) {
        // Load A tile: 16 c-rows x 128 n (512 float4), coalesced.
#pragma unroll
        for (int p4 = 0; p4 < 4; p4++) {
            int idx = p4 * 128 + tid;
            int c_l = idx >> 5;
            int n4  = idx & 31;
            float4 v = *reinterpret_cast<const float4*>(xb + (size_t)(k0 + c_l) * NN + n4 * 4);
            *reinterpret_cast<float4*>(&As[c_l][n4 * 4]) = v;
        }
        // Load B tile transposed: W[r, c] -> Bs[c][r] (256 float4 reads).
#pragma unroll
        for (int p4 = 0; p4 < 2; p4++) {
            int idx = p4 * 128 + tid;
            int r_l = idx >> 2;
            int c4  = idx & 3;
            float4 v = *reinterpret_cast<const float4*>(W + (size_t)r_l * CC + k0 + c4 * 4);
            Bs[c4 * 4 + 0][r_l] = v.x;
            Bs[c4 * 4 + 1][r_l] = v.y;
            Bs[c4 * 4 + 2][r_l] = v.z;
            Bs[c4 * 4 + 3][r_l] = v.w;
        }
        __syncthreads();
#pragma unroll
        for (int k = 0; k < 16; k++) {
            float4 a0 = *reinterpret_cast<float4*>(&As[k][ty * 4]);
            float4 a1 = *reinterpret_cast<float4*>(&As[k][64 + ty * 4]);
            float4 b0 = *reinterpret_cast<float4*>(&Bs[k][tx * 4]);
            float4 b1 = *reinterpret_cast<float4*>(&Bs[k][32 + tx * 4]);
            float av[8] = {a0.x, a0.y, a0.z, a0.w, a1.x, a1.y, a1.z, a1.w};
            float bv[8] = {b0.x, b0.y, b0.z, b0.w, b1.x, b1.y, b1.z, b1.w};
#pragma unroll
            for (int i = 0; i < 8; i++)
#pragma unroll
                for (int j = 0; j < 8; j++) acc[i][j] += av[i] * bv[j];
        }
        __syncthreads();
    }

    // Epilogue: add bias, write [b, n, r].
    float bvr[8];
#pragma unroll
    for (int j = 0; j < 4; j++) {
        bvr[j]     = bias[tx * 4 + j];
        bvr[4 + j] = bias[32 + tx * 4 + j];
    }
    float* ob = out + ((size_t)b * NN + n0) * RR;
#pragma unroll
    for (int i = 0; i < 8; i++) {
        int n = (i < 4) ? (ty * 4 + i) : (64 + ty * 4 + (i - 4));
#pragma unroll
        for (int h = 0; h < 2; h++) {
            float4 v;
            v.x = acc[i][h * 4 + 0] + bvr[h * 4 + 0];
            v.y = acc[i][h * 4 + 1] + bvr[h * 4 + 1];
            v.z = acc[i][h * 4 + 2] + bvr[h * 4 + 2];
            v.w = acc[i][h * 4 + 3] + bvr[h * 4 + 3];
            int r = (h == 0) ? (tx * 4) : (32 + tx * 4);
            *reinterpret_cast<float4*>(ob + (size_t)n * RR + r) = v;
        }
    }
}

// ---------------------------------------------------------------------------
// Kernel 2: attention with online softmax.
// Per block: batch b, 32 n-rows. Loop m-chunks of 64.
//   phase1: S[m][n] = scale * sum_r t[n,r] p[m,r]   (2n x 4m microtile)
//   phase2: online softmax over m (8-lane shfl groups per n row)
//   phase3: y[n,r] += w[m,n] * g[m,r]               (4n x 2r microtile)
// ---------------------------------------------------------------------------
__global__ __launch_bounds__(256) void attn_kernel()
{
    const int b  = blockIdx.y;
    const int n0 = blockIdx.x * 32;
    const int tid = threadIdx.x;

    __shared__ float tS[64][34];    // [r][n]
    __shared__ float buf[64][68];   // p chunk as [r][m]; then g chunk as [m][r]
    __shared__ float wS[64][36];    // scores/weights [m][n]
    __shared__ float fac_s[32];
    __shared__ float rsum_s[32];

    // Load t tile transposed: [n][r] -> tS[r][n]
    const float* tb = d_t + ((size_t)b * NN + n0) * RR;
    for (int i = tid; i < 512; i += 256) {           // 512 float4
        int n  = i >> 4;
        int r4 = (i & 15) * 4;
        float4 v = *reinterpret_cast<const float4*>(tb + (size_t)n * RR + r4);
        tS[r4 + 0][n] = v.x;
        tS[r4 + 1][n] = v.y;
        tS[r4 + 2][n] = v.z;
        tS[r4 + 3][n] = v.w;
    }

    // phase-1 mapping
    const int tx1 = tid & 15;   // m quad: tx1*4..+3
    const int ty1 = tid >> 4;   // n pair: ty1*2, ty1*2+1
    // phase-2 mapping
    const int n2 = tid >> 3;    // n row 0..31
    const int l8 = tid & 7;     // 8-lane group, handles m = l8 + 8k
    // phase-3 mapping
    const int tx3 = tid & 31;   // r pair: tx3*2
    const int ty3 = tid >> 5;   // n quad: ty3*4..+3

    float run_max = -1e30f, run_sum = 0.f;
    float yacc[4][2];
#pragma unroll
    for (int i = 0; i < 4; i++) { yacc[i][0] = 0.f; yacc[i][1] = 0.f; }

    const float* pb = d_p + (size_t)b * NN * RR;
    const float* gb = d_g + (size_t)b * NN * RR;

    __syncthreads();

    for (int m0 = 0; m0 < NN; m0 += 64) {
        // ---- Load p chunk transposed: [m][r] -> buf[r][m]
        for (int i = tid; i < 1024; i += 256) {      // 1024 float4 (64m x 16)
            int m  = i >> 4;
            int r4 = (i & 15) * 4;
            float4 v = *reinterpret_cast<const float4*>(pb + (size_t)(m0 + m) * RR + r4);
            buf[r4 + 0][m] = v.x;
            buf[r4 + 1][m] = v.y;
            buf[r4 + 2][m] = v.z;
            buf[r4 + 3][m] = v.w;
        }
        __syncthreads();

        // ---- Phase 1: scores (2n x 4m per thread)
        {
            float s[2][4];
#pragma unroll
            for (int i = 0; i < 2; i++)
#pragma unroll
                for (int j = 0; j < 4; j++) s[i][j] = 0.f;
#pragma unroll 16
            for (int r = 0; r < 64; r++) {
                float2 tv = *reinterpret_cast<float2*>(&tS[r][ty1 * 2]);
                float4 pv = *reinterpret_cast<float4*>(&buf[r][tx1 * 4]);
                s[0][0] += tv.x * pv.x; s[0][1] += tv.x * pv.y;
                s[0][2] += tv.x * pv.z; s[0][3] += tv.x * pv.w;
                s[1][0] += tv.y * pv.x; s[1][1] += tv.y * pv.y;
                s[1][2] += tv.y * pv.z; s[1][3] += tv.y * pv.w;
            }
#pragma unroll
            for (int j = 0; j < 4; j++) {
                wS[tx1 * 4 + j][ty1 * 2 + 0] = s[0][j] * SCALE;
                wS[tx1 * 4 + j][ty1 * 2 + 1] = s[1][j] * SCALE;
            }
        }
        __syncthreads();

        // ---- Load g chunk (direct, [m][r]) into buf  +  Phase 2 softmax
        for (int i = tid; i < 1024; i += 256) {
            int m  = i >> 4;
            int r4 = (i & 15) * 4;
            *reinterpret_cast<float4*>(&buf[m][r4]) =
                *reinterpret_cast<const float4*>(gb + (size_t)(m0 + m) * RR + r4);
        }
        {
            float sv[8];
#pragma unroll
            for (int k = 0; k < 8; k++) sv[k] = wS[l8 + 8 * k][n2];
            float mx = sv[0];
#pragma unroll
            for (int k = 1; k < 8; k++) mx = fmaxf(mx, sv[k]);
#pragma unroll
            for (int off = 4; off > 0; off >>= 1)
                mx = fmaxf(mx, __shfl_xor_sync(0xffffffffu, mx, off));
            float nmax = fmaxf(run_max, mx);
            float f    = __expf(run_max - nmax);
            float lsum = 0.f;
#pragma unroll
            for (int k = 0; k < 8; k++) {
                sv[k] = __expf(sv[k] - nmax);
                lsum += sv[k];
            }
#pragma unroll
            for (int off = 4; off > 0; off >>= 1)
                lsum += __shfl_xor_sync(0xffffffffu, lsum, off);
            run_sum = run_sum * f + lsum;
            run_max = nmax;
#pragma unroll
            for (int k = 0; k < 8; k++) wS[l8 + 8 * k][n2] = sv[k];
            if (l8 == 0) { fac_s[n2] = f; rsum_s[n2] = run_sum; }
        }
        __syncthreads();

        // ---- Phase 3: y update (4n x 2r per thread)
        {
#pragma unroll
            for (int i = 0; i < 4; i++) {
                float f = fac_s[ty3 * 4 + i];
                yacc[i][0] *= f;
                yacc[i][1] *= f;
            }
#pragma unroll 8
            for (int m = 0; m < 64; m++) {
                float4 wv = *reinterpret_cast<float4*>(&wS[m][ty3 * 4]);
                float2 gv = *reinterpret_cast<float2*>(&buf[m][tx3 * 2]);
                yacc[0][0] += wv.x * gv.x; yacc[0][1] += wv.x * gv.y;
                yacc[1][0] += wv.y * gv.x; yacc[1][1] += wv.y * gv.y;
                yacc[2][0] += wv.z * gv.x; yacc[2][1] += wv.z * gv.y;
                yacc[3][0] += wv.w * gv.x; yacc[3][1] += wv.w * gv.y;
            }
        }
        __syncthreads();
    }

    // Write y = acc / run_sum
    float* yb = d_y + ((size_t)b * NN + n0) * RR;
#pragma unroll
    for (int i = 0; i < 4; i++) {
        float inv = 1.f / rsum_s[ty3 * 4 + i];
        float2 v;
        v.x = yacc[i][0] * inv;
        v.y = yacc[i][1] * inv;
        *reinterpret_cast<float2*>(yb + (size_t)(ty3 * 4 + i) * RR + tx3 * 2) = v;
    }
}

// ---------------------------------------------------------------------------
// Kernel 3: z = y @ Wz^T + bz, then BN(inference) + residual.
// out[b,c,n] = (sum_r y[b,n,r] Wz[c,r] + bz[c] - mean[c]) * rsqrt(var+eps)
//              * gamma[c] + beta[c] + x[b,c,n]
// Tile 64c x 64n, K=64 single stage, 256 threads, 4x4 microtile.
// ---------------------------------------------------------------------------
__global__ __launch_bounds__(256) void out_kernel(
    const float* __restrict__ x,
    const float* __restrict__ Wz, const float* __restrict__ bz,
    const float* __restrict__ gamma, const float* __restrict__ beta,
    const float* __restrict__ bn_mean, const float* __restrict__ bn_var,
    float* __restrict__ out)
{
    const int b  = blockIdx.z;
    const int c0 = blockIdx.y * 64;
    const int n0 = blockIdx.x * 64;
    const int tid = threadIdx.x;
    const int tx = tid & 15;   // n quad
    const int ty = tid >> 4;   // c quad

    __shared__ float yS[64][68];   // [r][n]
    __shared__ float wzS[64][68];  // [r][c]

    const float* yb = d_y + ((size_t)b * NN + n0) * RR;
    for (int i = tid; i < 1024; i += 256) {
        int n  = i >> 4;
        int r4 = (i & 15) * 4;
        float4 v = *reinterpret_cast<const float4*>(yb + (size_t)n * RR + r4);
        yS[r4 + 0][n] = v.x;
        yS[r4 + 1][n] = v.y;
        yS[r4 + 2][n] = v.z;
        yS[r4 + 3][n] = v.w;
    }
    for (int i = tid; i < 1024; i += 256) {
        int c  = i >> 4;
        int r4 = (i & 15) * 4;
        float4 v = *reinterpret_cast<const float4*>(Wz + (size_t)(c0 + c) * RR + r4);
        wzS[r4 + 0][c] = v.x;
        wzS[r4 + 1][c] = v.y;
        wzS[r4 + 2][c] = v.z;
        wzS[r4 + 3][c] = v.w;
    }
    __syncthreads();

    float acc[4][4];
#pragma unroll
    for (int i = 0; i < 4; i++)
#pragma unroll
        for (int j = 0; j < 4; j++) acc[i][j] = 0.f;

#pragma unroll 16
    for (int r = 0; r < 64; r++) {
        float4 cv = *reinterpret_cast<float4*>(&wzS[r][ty * 4]);
        float4 nv = *reinterpret_cast<float4*>(&yS[r][tx * 4]);
        acc[0][0] += cv.x * nv.x; acc[0][1] += cv.x * nv.y; acc[0][2] += cv.x * nv.z; acc[0][3] += cv.x * nv.w;
        acc[1][0] += cv.y * nv.x; acc[1][1] += cv.y * nv.y; acc[1][2] += cv.y * nv.z; acc[1][3] += cv.y * nv.w;
        acc[2][0] += cv.z * nv.x; acc[2][1] += cv.z * nv.y; acc[2][2] += cv.z * nv.z; acc[2][3] += cv.z * nv.w;
        acc[3][0] += cv.w * nv.x; acc[3][1] += cv.w * nv.y; acc[3][2] += cv.w * nv.z; acc[3][3] += cv.w * nv.w;
    }

    // Epilogue
#pragma unroll
    for (int i = 0; i < 4; i++) {
        int c = c0 + ty * 4 + i;
        float a   = rsqrtf(bn_var[c] + EPS) * gamma[c];
        float off = (bz[c] - bn_mean[c]) * a + beta[c];
        size_t base = (size_t)b * CC * NN + (size_t)c * NN + n0 + tx * 4;
        float4 xv = *reinterpret_cast<const float4*>(x + base);
        float4 o;
        o.x = acc[i][0] * a + off + xv.x;
        o.y = acc[i][1] * a + off + xv.y;
        o.z = acc[i][2] * a + off + xv.z;
        o.w = acc[i][3] * a + off + xv.w;
        *reinterpret_cast<float4*>(out + base) = o;
    }
}

// ---------------------------------------------------------------------------
extern "C" void kernel_launch(void* const* d_in, const int* in_sizes, int n_in,
                              void* d_out, int out_size)
{
    (void)in_sizes; (void)n_in; (void)out_size;
    const float* x       = (const float*)d_in[0];
    const float* Wt      = (const float*)d_in[1];
    const float* bt      = (const float*)d_in[2];
    const float* Wp      = (const float*)d_in[3];
    const float* bp      = (const float*)d_in[4];
    const float* Wg      = (const float*)d_in[5];
    const float* bg      = (const float*)d_in[6];
    const float* Wz      = (const float*)d_in[7];
    const float* bz      = (const float*)d_in[8];
    const float* gamma   = (const float*)d_in[9];
    const float* beta    = (const float*)d_in[10];
    const float* bn_mean = (const float*)d_in[11];
    const float* bn_var  = (const float*)d_in[12];
    float* out = (float*)d_out;

    proj_kernel<<<dim3(256, 1, 3), 128>>>(x, Wt, bt, Wp, bp, Wg, bg);
    attn_kernel<<<dim3(32, 32), 256>>>();
    out_kernel<<<dim3(16, 8, 32), 256>>>(x, Wz, bz, gamma, beta, bn_mean, bn_var, out);
}

// round 3
// speedup vs baseline: 1.1888x; 1.1875x over previous
#include <cuda_runtime.h>
#include <math.h>

#define BB 32
#define CC 512
#define NN 1024
#define RR 64
#define EPS 1e-5f
#define SCALE 0.04419417382415922f

typedef unsigned long long u64;

__device__ __forceinline__ void fma2(u64 &d, u64 a, u64 b) {
    asm("fma.rn.f32x2 %0,%1,%2,%0;" : "+l"(d) : "l"(a), "l"(b));
}
__device__ __forceinline__ u64 dup2(float x) {
    u64 r; unsigned xi = __float_as_uint(x);
    asm("mov.b64 %0,{%1,%1};" : "=l"(r) : "r"(xi)); return r;
}
__device__ __forceinline__ float2 up2(u64 v) {
    float2 r; asm("mov.b64 {%0,%1},%2;" : "=f"(r.x), "=f"(r.y) : "l"(v)); return r;
}
__device__ __forceinline__ u64 mul2u(u64 a, u64 b) {
    u64 r; asm("mul.rn.f32x2 %0,%1,%2;" : "=l"(r) : "l"(a), "l"(b)); return r;
}

__device__ float d_t[BB * NN * RR];
__device__ float d_p[BB * NN * RR];
__device__ float d_g[BB * NN * RR];
__device__ float d_y[BB * NN * RR];

// ---------------------------------------------------------------------------
// K1: projections. out[b,n,r] = sum_c x[b,c,n]*W[r,c] + bias[r]
// 128n x 64r tile, BK=16, 128 threads, 8n x 8r microtile, FFMA2 packed on n.
// ---------------------------------------------------------------------------
__global__ __launch_bounds__(128) void proj_kernel(
    const float* __restrict__ x,
    const float* __restrict__ Wt, const float* __restrict__ bt,
    const float* __restrict__ Wp, const float* __restrict__ bp,
    const float* __restrict__ Wg, const float* __restrict__ bg)
{
    const int which = blockIdx.z;
    const float* W    = (which == 0) ? Wt : (which == 1) ? Wp : Wg;
    const float* bias = (which == 0) ? bt : (which == 1) ? bp : bg;
    float* out        = (which == 0) ? d_t : (which == 1) ? d_p : d_g;

    const int tile = blockIdx.x;
    const int b    = tile >> 3;
    const int n0   = (tile & 7) << 7;
    const int tid  = threadIdx.x;
    const int tx   = tid & 7;     // r octet
    const int ty   = tid >> 3;    // n octet (16)

    __shared__ __align__(16) float As[16][132];
    __shared__ __align__(16) float Bs[16][68];

    u64 acc[4][8];   // [n-pair][r]
#pragma unroll
    for (int i = 0; i < 4; i++)
#pragma unroll
        for (int j = 0; j < 8; j++) acc[i][j] = 0ull;

    const float* xb = x + (size_t)b * CC * NN + n0;

    for (int k0 = 0; k0 < CC; k0 += 16) {
#pragma unroll
        for (int p4 = 0; p4 < 4; p4++) {
            int idx = p4 * 128 + tid;
            int c_l = idx >> 5;
            int n4  = (idx & 31) * 4;
            *reinterpret_cast<float4*>(&As[c_l][n4]) =
                *reinterpret_cast<const float4*>(xb + (size_t)(k0 + c_l) * NN + n4);
        }
#pragma unroll
        for (int p4 = 0; p4 < 2; p4++) {
            int idx = p4 * 128 + tid;
            int r_l = idx >> 2;
            int c4  = (idx & 3) * 4;
            float4 v = *reinterpret_cast<const float4*>(W + (size_t)r_l * CC + k0 + c4);
            Bs[c4 + 0][r_l] = v.x; Bs[c4 + 1][r_l] = v.y;
            Bs[c4 + 2][r_l] = v.z; Bs[c4 + 3][r_l] = v.w;
        }
        __syncthreads();
#pragma unroll
        for (int k = 0; k < 16; k++) {
            ulonglong2 A0 = *reinterpret_cast<ulonglong2*>(&As[k][ty * 4]);
            ulonglong2 A1 = *reinterpret_cast<ulonglong2*>(&As[k][64 + ty * 4]);
            u64 ap[4] = {A0.x, A0.y, A1.x, A1.y};
            float4 b0 = *reinterpret_cast<float4*>(&Bs[k][tx * 8]);
            float4 b1 = *reinterpret_cast<float4*>(&Bs[k][tx * 8 + 4]);
            u64 bd[8] = {dup2(b0.x), dup2(b0.y), dup2(b0.z), dup2(b0.w),
                         dup2(b1.x), dup2(b1.y), dup2(b1.z), dup2(b1.w)};
#pragma unroll
            for (int i = 0; i < 4; i++)
#pragma unroll
                for (int j = 0; j < 8; j++) fma2(acc[i][j], ap[i], bd[j]);
        }
        __syncthreads();
    }

    float bv[8];
#pragma unroll
    for (int j = 0; j < 8; j++) bv[j] = bias[tx * 8 + j];
    float* ob = out + ((size_t)b * NN + n0) * RR;
#pragma unroll
    for (int i = 0; i < 4; i++) {
        float2 v[8];
#pragma unroll
        for (int j = 0; j < 8; j++) v[j] = up2(acc[i][j]);
        int n = (i < 2) ? (ty * 4 + 2 * i) : (64 + ty * 4 + 2 * (i - 2));
        float4 w0, w1, w2, w3;
        w0.x = v[0].x + bv[0]; w0.y = v[1].x + bv[1]; w0.z = v[2].x + bv[2]; w0.w = v[3].x + bv[3];
        w1.x = v[4].x + bv[4]; w1.y = v[5].x + bv[5]; w1.z = v[6].x + bv[6]; w1.w = v[7].x + bv[7];
        w2.x = v[0].y + bv[0]; w2.y = v[1].y + bv[1]; w2.z = v[2].y + bv[2]; w2.w = v[3].y + bv[3];
        w3.x = v[4].y + bv[4]; w3.y = v[5].y + bv[5]; w3.z = v[6].y + bv[6]; w3.w = v[7].y + bv[7];
        *reinterpret_cast<float4*>(ob + (size_t)n * RR + tx * 8)           = w0;
        *reinterpret_cast<float4*>(ob + (size_t)n * RR + tx * 8 + 4)       = w1;
        *reinterpret_cast<float4*>(ob + (size_t)(n + 1) * RR + tx * 8)     = w2;
        *reinterpret_cast<float4*>(ob + (size_t)(n + 1) * RR + tx * 8 + 4) = w3;
    }
}

// ---------------------------------------------------------------------------
// K2: attention, 64 n-rows per block, m-chunks of 64, online softmax.
// Dynamic smem: tS[64][68] ([r][n]), buf[64][68] (p as [r][m], then g [m][r]),
// wS[64][68] ([m][n]), fac[64], rsum[64].  52.7 KB -> 2 blocks/SM.
// ---------------------------------------------------------------------------
__global__ __launch_bounds__(256) void attn_kernel()
{
    extern __shared__ float sm[];
    float (*tS)[68]  = (float(*)[68])sm;
    float (*buf)[68] = (float(*)[68])(sm + 64 * 68);
    float (*wS)[68]  = (float(*)[68])(sm + 2 * 64 * 68);
    float* fac_s  = sm + 3 * 64 * 68;
    float* rsum_s = fac_s + 64;

    const int b   = blockIdx.y;
    const int n0  = blockIdx.x * 64;
    const int tid = threadIdx.x;
    const int tx  = tid & 15;    // quad (m in ph1, r in ph3)
    const int ty  = tid >> 4;    // n quad
    const int n2  = tid >> 2;    // softmax row
    const int l4  = tid & 3;     // softmax lane

    const float* tb = d_t + ((size_t)b * NN + n0) * RR;
    for (int i = tid; i < 1024; i += 256) {
        int n = i >> 4, r4 = (i & 15) * 4;
        float4 v = *reinterpret_cast<const float4*>(tb + (size_t)n * RR + r4);
        tS[r4 + 0][n] = v.x; tS[r4 + 1][n] = v.y;
        tS[r4 + 2][n] = v.z; tS[r4 + 3][n] = v.w;
    }

    float run_max = -1e30f, run_sum = 0.f;
    u64 yacc[4][2];   // [n][r-pair]
#pragma unroll
    for (int i = 0; i < 4; i++) { yacc[i][0] = 0ull; yacc[i][1] = 0ull; }

    const float* pb = d_p + (size_t)b * NN * RR;
    const float* gb = d_g + (size_t)b * NN * RR;
    __syncthreads();

    for (int m0 = 0; m0 < NN; m0 += 64) {
        // load p transposed: [m][r] -> buf[r][m]
        for (int i = tid; i < 1024; i += 256) {
            int m = i >> 4, r4 = (i & 15) * 4;
            float4 v = *reinterpret_cast<const float4*>(pb + (size_t)(m0 + m) * RR + r4);
            buf[r4 + 0][m] = v.x; buf[r4 + 1][m] = v.y;
            buf[r4 + 2][m] = v.z; buf[r4 + 3][m] = v.w;
        }
        __syncthreads();

        // phase 1: s[n][m] , 4n x 4m per thread, packed on m
        {
            u64 s[4][2];
#pragma unroll
            for (int i = 0; i < 4; i++) { s[i][0] = 0ull; s[i][1] = 0ull; }
#pragma unroll 8
            for (int r = 0; r < 64; r++) {
                float4 tv = *reinterpret_cast<float4*>(&tS[r][ty * 4]);
                ulonglong2 pv = *reinterpret_cast<ulonglong2*>(&buf[r][tx * 4]);
                u64 td[4] = {dup2(tv.x), dup2(tv.y), dup2(tv.z), dup2(tv.w)};
#pragma unroll
                for (int i = 0; i < 4; i++) {
                    fma2(s[i][0], td[i], pv.x);
                    fma2(s[i][1], td[i], pv.y);
                }
            }
#pragma unroll
            for (int p = 0; p < 2; p++) {
                float2 u[4];
#pragma unroll
                for (int i = 0; i < 4; i++) u[i] = up2(s[i][p]);
                float4 w0 = {u[0].x * SCALE, u[1].x * SCALE, u[2].x * SCALE, u[3].x * SCALE};
                float4 w1 = {u[0].y * SCALE, u[1].y * SCALE, u[2].y * SCALE, u[3].y * SCALE};
                *reinterpret_cast<float4*>(&wS[tx * 4 + 2 * p][ty * 4])     = w0;
                *reinterpret_cast<float4*>(&wS[tx * 4 + 2 * p + 1][ty * 4]) = w1;
            }
        }
        __syncthreads();

        // load g (direct) + softmax
        for (int i = tid; i < 1024; i += 256) {
            int m = i >> 4, r4 = (i & 15) * 4;
            *reinterpret_cast<float4*>(&buf[m][r4]) =
                *reinterpret_cast<const float4*>(gb + (size_t)(m0 + m) * RR + r4);
        }
        {
            float sv[16];
#pragma unroll
            for (int k = 0; k < 16; k++) sv[k] = wS[l4 + 4 * k][n2];
            float mx = sv[0];
#pragma unroll
            for (int k = 1; k < 16; k++) mx = fmaxf(mx, sv[k]);
            mx = fmaxf(mx, __shfl_xor_sync(0xffffffffu, mx, 1));
            mx = fmaxf(mx, __shfl_xor_sync(0xffffffffu, mx, 2));
            float nmax = fmaxf(run_max, mx);
            float f = __expf(run_max - nmax);
            float lsum = 0.f;
#pragma unroll
            for (int k = 0; k < 16; k++) { sv[k] = __expf(sv[k] - nmax); lsum += sv[k]; }
            lsum += __shfl_xor_sync(0xffffffffu, lsum, 1);
            lsum += __shfl_xor_sync(0xffffffffu, lsum, 2);
            run_sum = run_sum * f + lsum;
            run_max = nmax;
#pragma unroll
            for (int k = 0; k < 16; k++) wS[l4 + 4 * k][n2] = sv[k];
            if (l4 == 0) { fac_s[n2] = f; rsum_s[n2] = run_sum; }
        }
        __syncthreads();

        // phase 3: y[n][r] += w[m][n]*g[m][r], 4n x 4r per thread, packed on r
        {
#pragma unroll
            for (int i = 0; i < 4; i++) {
                u64 fd = dup2(fac_s[ty * 4 + i]);
                yacc[i][0] = mul2u(yacc[i][0], fd);
                yacc[i][1] = mul2u(yacc[i][1], fd);
            }
#pragma unroll 8
            for (int m = 0; m < 64; m++) {
                float4 wv = *reinterpret_cast<float4*>(&wS[m][ty * 4]);
                ulonglong2 gv = *reinterpret_cast<ulonglong2*>(&buf[m][tx * 4]);
                u64 wd[4] = {dup2(wv.x), dup2(wv.y), dup2(wv.z), dup2(wv.w)};
#pragma unroll
                for (int i = 0; i < 4; i++) {
                    fma2(yacc[i][0], wd[i], gv.x);
                    fma2(yacc[i][1], wd[i], gv.y);
                }
            }
        }
        __syncthreads();
    }

    float* yb = d_y + ((size_t)b * NN + n0) * RR;
#pragma unroll
    for (int i = 0; i < 4; i++) {
        float inv = 1.f / rsum_s[ty * 4 + i];
        float2 a = up2(yacc[i][0]), c = up2(yacc[i][1]);
        float4 o = {a.x * inv, a.y * inv, c.x * inv, c.y * inv};
        *reinterpret_cast<float4*>(yb + (size_t)(ty * 4 + i) * RR + tx * 4) = o;
    }
}

// ---------------------------------------------------------------------------
// K3: z = y @ Wz^T + bz, BN inference + residual. 64c x 64n, K=64, 256 thr.
// ---------------------------------------------------------------------------
__global__ __launch_bounds__(256) void out_kernel(
    const float* __restrict__ x,
    const float* __restrict__ Wz, const float* __restrict__ bz,
    const float* __restrict__ gamma, const float* __restrict__ beta,
    const float* __restrict__ bn_mean, const float* __restrict__ bn_var,
    float* __restrict__ out)
{
    const int b  = blockIdx.z;
    const int c0 = blockIdx.y * 64;
    const int n0 = blockIdx.x * 64;
    const int tid = threadIdx.x;
    const int tx = tid & 15;   // n quad
    const int ty = tid >> 4;   // c quad

    __shared__ __align__(16) float yS[64][68];
    __shared__ __align__(16) float wzS[64][68];

    const float* yb = d_y + ((size_t)b * NN + n0) * RR;
    for (int i = tid; i < 1024; i += 256) {
        int n = i >> 4, r4 = (i & 15) * 4;
        float4 v = *reinterpret_cast<const float4*>(yb + (size_t)n * RR + r4);
        yS[r4 + 0][n] = v.x; yS[r4 + 1][n] = v.y;
        yS[r4 + 2][n] = v.z; yS[r4 + 3][n] = v.w;
    }
    for (int i = tid; i < 1024; i += 256) {
        int c = i >> 4, r4 = (i & 15) * 4;
        float4 v = *reinterpret_cast<const float4*>(Wz + (size_t)(c0 + c) * RR + r4);
        wzS[r4 + 0][c] = v.x; wzS[r4 + 1][c] = v.y;
        wzS[r4 + 2][c] = v.z; wzS[r4 + 3][c] = v.w;
    }
    __syncthreads();

    u64 acc[4][2];   // [c][n-pair]
#pragma unroll
    for (int i = 0; i < 4; i++) { acc[i][0] = 0ull; acc[i][1] = 0ull; }

#pragma unroll 8
    for (int r = 0; r < 64; r++) {
        float4 cv = *reinterpret_cast<float4*>(&wzS[r][ty * 4]);
        ulonglong2 nv = *reinterpret_cast<ulonglong2*>(&yS[r][tx * 4]);
        u64 cd[4] = {dup2(cv.x), dup2(cv.y), dup2(cv.z), dup2(cv.w)};
#pragma unroll
        for (int i = 0; i < 4; i++) {
            fma2(acc[i][0], cd[i], nv.x);
            fma2(acc[i][1], cd[i], nv.y);
        }
    }

#pragma unroll
    for (int i = 0; i < 4; i++) {
        int c = c0 + ty * 4 + i;
        float a   = rsqrtf(bn_var[c] + EPS) * gamma[c];
        float off = (bz[c] - bn_mean[c]) * a + beta[c];
        size_t base = (size_t)b * CC * NN + (size_t)c * NN + n0 + tx * 4;
        float4 xv = *reinterpret_cast<const float4*>(x + base);
        float2 pa = up2(acc[i][0]), pc = up2(acc[i][1]);
        float4 o;
        o.x = pa.x * a + off + xv.x;
        o.y = pa.y * a + off + xv.y;
        o.z = pc.x * a + off + xv.z;
        o.w = pc.y * a + off + xv.w;
        *reinterpret_cast<float4*>(out + base) = o;
    }
}

// ---------------------------------------------------------------------------
#define ATTN_SMEM (int)((3 * 64 * 68 + 128) * sizeof(float))

extern "C" void kernel_launch(void* const* d_in, const int* in_sizes, int n_in,
                              void* d_out, int out_size)
{
    (void)in_sizes; (void)n_in; (void)out_size;
    const float* x       = (const float*)d_in[0];
    const float* Wt      = (const float*)d_in[1];
    const float* bt      = (const float*)d_in[2];
    const float* Wp      = (const float*)d_in[3];
    const float* bp      = (const float*)d_in[4];
    const float* Wg      = (const float*)d_in[5];
    const float* bg      = (const float*)d_in[6];
    const float* Wz      = (const float*)d_in[7];
    const float* bz      = (const float*)d_in[8];
    const float* gamma   = (const float*)d_in[9];
    const float* beta    = (const float*)d_in[10];
    const float* bn_mean = (const float*)d_in[11];
    const float* bn_var  = (const float*)d_in[12];
    float* out = (float*)d_out;

    cudaFuncSetAttribute(attn_kernel, cudaFuncAttributeMaxDynamicSharedMemorySize, ATTN_SMEM);

    proj_kernel<<<dim3(256, 1, 3), 128>>>(x, Wt, bt, Wp, bp, Wg, bg);
    attn_kernel<<<dim3(16, 32), 256, ATTN_SMEM>>>();
    out_kernel<<<dim3(16, 8, 32), 256>>>(x, Wz, bz, gamma, beta, bn_mean, bn_var, out);
}

// round 4
// speedup vs baseline: 1.1946x; 1.0048x over previous
#include <cuda_runtime.h>
#include <math.h>

#define BB 32
#define CC 512
#define NN 1024
#define RR 64
#define EPS 1e-5f
#define SCALE 0.04419417382415922f

typedef unsigned long long u64;

__device__ __forceinline__ void fma2(u64 &d, u64 a, u64 b) {
    asm("fma.rn.f32x2 %0,%1,%2,%0;" : "+l"(d) : "l"(a), "l"(b));
}
__device__ __forceinline__ u64 dup2(float x) {
    u64 r; unsigned xi = __float_as_uint(x);
    asm("mov.b64 %0,{%1,%1};" : "=l"(r) : "r"(xi)); return r;
}
__device__ __forceinline__ float2 up2(u64 v) {
    float2 r; asm("mov.b64 {%0,%1},%2;" : "=f"(r.x), "=f"(r.y) : "l"(v)); return r;
}
__device__ __forceinline__ u64 mul2u(u64 a, u64 b) {
    u64 r; asm("mul.rn.f32x2 %0,%1,%2;" : "=l"(r) : "l"(a), "l"(b)); return r;
}

__device__ float d_t[BB * NN * RR];
__device__ float d_p[BB * NN * RR];
__device__ float d_g[BB * NN * RR];
__device__ float d_y[BB * NN * RR];

// ---------------------------------------------------------------------------
// K1: projections. out[b,n,r] = sum_c x[b,c,n]*W[r,c] + bias[r]
// 128n x 64r tile, BK=16, 128 threads, 8n x 8r microtile, FFMA2 packed on n.
// ---------------------------------------------------------------------------
__global__ __launch_bounds__(128) void proj_kernel(
    const float* __restrict__ x,
    const float* __restrict__ Wt, const float* __restrict__ bt,
    const float* __restrict__ Wp, const float* __restrict__ bp,
    const float* __restrict__ Wg, const float* __restrict__ bg)
{
    const int which = blockIdx.z;
    const float* W    = (which == 0) ? Wt : (which == 1) ? Wp : Wg;
    const float* bias = (which == 0) ? bt : (which == 1) ? bp : bg;
    float* out        = (which == 0) ? d_t : (which == 1) ? d_p : d_g;

    const int tile = blockIdx.x;
    const int b    = tile >> 3;
    const int n0   = (tile & 7) << 7;
    const int tid  = threadIdx.x;
    const int tx   = tid & 7;     // r octet
    const int ty   = tid >> 3;    // n octet (16)

    __shared__ __align__(16) float As[16][132];
    __shared__ __align__(16) float Bs[16][68];

    u64 acc[4][8];   // [n-pair][r]
#pragma unroll
    for (int i = 0; i < 4; i++)
#pragma unroll
        for (int j = 0; j < 8; j++) acc[i][j] = 0ull;

    const float* xb = x + (size_t)b * CC * NN + n0;

    for (int k0 = 0; k0 < CC; k0 += 16) {
#pragma unroll
        for (int p4 = 0; p4 < 4; p4++) {
            int idx = p4 * 128 + tid;
            int c_l = idx >> 5;
            int n4  = (idx & 31) * 4;
            *reinterpret_cast<float4*>(&As[c_l][n4]) =
                *reinterpret_cast<const float4*>(xb + (size_t)(k0 + c_l) * NN + n4);
        }
#pragma unroll
        for (int p4 = 0; p4 < 2; p4++) {
            int idx = p4 * 128 + tid;
            int r_l = idx >> 2;
            int c4  = (idx & 3) * 4;
            float4 v = *reinterpret_cast<const float4*>(W + (size_t)r_l * CC + k0 + c4);
            Bs[c4 + 0][r_l] = v.x; Bs[c4 + 1][r_l] = v.y;
            Bs[c4 + 2][r_l] = v.z; Bs[c4 + 3][r_l] = v.w;
        }
        __syncthreads();
#pragma unroll
        for (int k = 0; k < 16; k++) {
            ulonglong2 A0 = *reinterpret_cast<ulonglong2*>(&As[k][ty * 4]);
            ulonglong2 A1 = *reinterpret_cast<ulonglong2*>(&As[k][64 + ty * 4]);
            u64 ap[4] = {A0.x, A0.y, A1.x, A1.y};
            float4 b0 = *reinterpret_cast<float4*>(&Bs[k][tx * 8]);
            float4 b1 = *reinterpret_cast<float4*>(&Bs[k][tx * 8 + 4]);
            u64 bd[8] = {dup2(b0.x), dup2(b0.y), dup2(b0.z), dup2(b0.w),
                         dup2(b1.x), dup2(b1.y), dup2(b1.z), dup2(b1.w)};
#pragma unroll
            for (int i = 0; i < 4; i++)
#pragma unroll
                for (int j = 0; j < 8; j++) fma2(acc[i][j], ap[i], bd[j]);
        }
        __syncthreads();
    }

    float bv[8];
#pragma unroll
    for (int j = 0; j < 8; j++) bv[j] = bias[tx * 8 + j];
    float* ob = out + ((size_t)b * NN + n0) * RR;
#pragma unroll
    for (int i = 0; i < 4; i++) {
        float2 v[8];
#pragma unroll
        for (int j = 0; j < 8; j++) v[j] = up2(acc[i][j]);
        int n = (i < 2) ? (ty * 4 + 2 * i) : (64 + ty * 4 + 2 * (i - 2));
        float4 w0, w1, w2, w3;
        w0.x = v[0].x + bv[0]; w0.y = v[1].x + bv[1]; w0.z = v[2].x + bv[2]; w0.w = v[3].x + bv[3];
        w1.x = v[4].x + bv[4]; w1.y = v[5].x + bv[5]; w1.z = v[6].x + bv[6]; w1.w = v[7].x + bv[7];
        w2.x = v[0].y + bv[0]; w2.y = v[1].y + bv[1]; w2.z = v[2].y + bv[2]; w2.w = v[3].y + bv[3];
        w3.x = v[4].y + bv[4]; w3.y = v[5].y + bv[5]; w3.z = v[6].y + bv[6]; w3.w = v[7].y + bv[7];
        *reinterpret_cast<float4*>(ob + (size_t)n * RR + tx * 8)           = w0;
        *reinterpret_cast<float4*>(ob + (size_t)n * RR + tx * 8 + 4)       = w1;
        *reinterpret_cast<float4*>(ob + (size_t)(n + 1) * RR + tx * 8)     = w2;
        *reinterpret_cast<float4*>(ob + (size_t)(n + 1) * RR + tx * 8 + 4) = w3;
    }
}

// ---------------------------------------------------------------------------
// K2: attention, 64 n-rows per block, m-chunks of 64, online softmax.
// Dynamic smem: tS[64][68] ([r][n]), buf[64][68] (p as [r][m], then g [m][r]),
// wS[64][68] ([m][n]), fac[64], rsum[64].  52.7 KB -> 2 blocks/SM.
// ---------------------------------------------------------------------------
__global__ __launch_bounds__(256) void attn_kernel()
{
    extern __shared__ float sm[];
    float (*tS)[68]  = (float(*)[68])sm;
    float (*buf)[68] = (float(*)[68])(sm + 64 * 68);
    float (*wS)[68]  = (float(*)[68])(sm + 2 * 64 * 68);
    float* fac_s  = sm + 3 * 64 * 68;
    float* rsum_s = fac_s + 64;

    const int b   = blockIdx.y;
    const int n0  = blockIdx.x * 64;
    const int tid = threadIdx.x;
    const int tx  = tid & 15;    // quad (m in ph1, r in ph3)
    const int ty  = tid >> 4;    // n quad
    const int n2  = tid >> 2;    // softmax row
    const int l4  = tid & 3;     // softmax lane

    const float* tb = d_t + ((size_t)b * NN + n0) * RR;
    for (int i = tid; i < 1024; i += 256) {
        int n = i >> 4, r4 = (i & 15) * 4;
        float4 v = *reinterpret_cast<const float4*>(tb + (size_t)n * RR + r4);
        tS[r4 + 0][n] = v.x; tS[r4 + 1][n] = v.y;
        tS[r4 + 2][n] = v.z; tS[r4 + 3][n] = v.w;
    }

    float run_max = -1e30f, run_sum = 0.f;
    u64 yacc[4][2];   // [n][r-pair]
#pragma unroll
    for (int i = 0; i < 4; i++) { yacc[i][0] = 0ull; yacc[i][1] = 0ull; }

    const float* pb = d_p + (size_t)b * NN * RR;
    const float* gb = d_g + (size_t)b * NN * RR;
    __syncthreads();

    for (int m0 = 0; m0 < NN; m0 += 64) {
        // load p transposed: [m][r] -> buf[r][m]
        for (int i = tid; i < 1024; i += 256) {
            int m = i >> 4, r4 = (i & 15) * 4;
            float4 v = *reinterpret_cast<const float4*>(pb + (size_t)(m0 + m) * RR + r4);
            buf[r4 + 0][m] = v.x; buf[r4 + 1][m] = v.y;
            buf[r4 + 2][m] = v.z; buf[r4 + 3][m] = v.w;
        }
        __syncthreads();

        // phase 1: s[n][m] , 4n x 4m per thread, packed on m
        {
            u64 s[4][2];
#pragma unroll
            for (int i = 0; i < 4; i++) { s[i][0] = 0ull; s[i][1] = 0ull; }
#pragma unroll 8
            for (int r = 0; r < 64; r++) {
                float4 tv = *reinterpret_cast<float4*>(&tS[r][ty * 4]);
                ulonglong2 pv = *reinterpret_cast<ulonglong2*>(&buf[r][tx * 4]);
                u64 td[4] = {dup2(tv.x), dup2(tv.y), dup2(tv.z), dup2(tv.w)};
#pragma unroll
                for (int i = 0; i < 4; i++) {
                    fma2(s[i][0], td[i], pv.x);
                    fma2(s[i][1], td[i], pv.y);
                }
            }
#pragma unroll
            for (int p = 0; p < 2; p++) {
                float2 u[4];
#pragma unroll
                for (int i = 0; i < 4; i++) u[i] = up2(s[i][p]);
                float4 w0 = {u[0].x * SCALE, u[1].x * SCALE, u[2].x * SCALE, u[3].x * SCALE};
                float4 w1 = {u[0].y * SCALE, u[1].y * SCALE, u[2].y * SCALE, u[3].y * SCALE};
                *reinterpret_cast<float4*>(&wS[tx * 4 + 2 * p][ty * 4])     = w0;
                *reinterpret_cast<float4*>(&wS[tx * 4 + 2 * p + 1][ty * 4]) = w1;
            }
        }
        __syncthreads();

        // load g (direct) + softmax
        for (int i = tid; i < 1024; i += 256) {
            int m = i >> 4, r4 = (i & 15) * 4;
            *reinterpret_cast<float4*>(&buf[m][r4]) =
                *reinterpret_cast<const float4*>(gb + (size_t)(m0 + m) * RR + r4);
        }
        {
            float sv[16];
#pragma unroll
            for (int k = 0; k < 16; k++) sv[k] = wS[l4 + 4 * k][n2];
            float mx = sv[0];
#pragma unroll
            for (int k = 1; k < 16; k++) mx = fmaxf(mx, sv[k]);
            mx = fmaxf(mx, __shfl_xor_sync(0xffffffffu, mx, 1));
            mx = fmaxf(mx, __shfl_xor_sync(0xffffffffu, mx, 2));
            float nmax = fmaxf(run_max, mx);
            float f = __expf(run_max - nmax);
            float lsum = 0.f;
#pragma unroll
            for (int k = 0; k < 16; k++) { sv[k] = __expf(sv[k] - nmax); lsum += sv[k]; }
            lsum += __shfl_xor_sync(0xffffffffu, lsum, 1);
            lsum += __shfl_xor_sync(0xffffffffu, lsum, 2);
            run_sum = run_sum * f + lsum;
            run_max = nmax;
#pragma unroll
            for (int k = 0; k < 16; k++) wS[l4 + 4 * k][n2] = sv[k];
            if (l4 == 0) { fac_s[n2] = f; rsum_s[n2] = run_sum; }
        }
        __syncthreads();

        // phase 3: y[n][r] += w[m][n]*g[m][r], 4n x 4r per thread, packed on r
        {
#pragma unroll
            for (int i = 0; i < 4; i++) {
                u64 fd = dup2(fac_s[ty * 4 + i]);
                yacc[i][0] = mul2u(yacc[i][0], fd);
                yacc[i][1] = mul2u(yacc[i][1], fd);
            }
#pragma unroll 8
            for (int m = 0; m < 64; m++) {
                float4 wv = *reinterpret_cast<float4*>(&wS[m][ty * 4]);
                ulonglong2 gv = *reinterpret_cast<ulonglong2*>(&buf[m][tx * 4]);
                u64 wd[4] = {dup2(wv.x), dup2(wv.y), dup2(wv.z), dup2(wv.w)};
#pragma unroll
                for (int i = 0; i < 4; i++) {
                    fma2(yacc[i][0], wd[i], gv.x);
                    fma2(yacc[i][1], wd[i], gv.y);
                }
            }
        }
        __syncthreads();
    }

    float* yb = d_y + ((size_t)b * NN + n0) * RR;
#pragma unroll
    for (int i = 0; i < 4; i++) {
        float inv = 1.f / rsum_s[ty * 4 + i];
        float2 a = up2(yacc[i][0]), c = up2(yacc[i][1]);
        float4 o = {a.x * inv, a.y * inv, c.x * inv, c.y * inv};
        *reinterpret_cast<float4*>(yb + (size_t)(ty * 4 + i) * RR + tx * 4) = o;
    }
}

// ---------------------------------------------------------------------------
// K3: z = y @ Wz^T + bz, BN inference + residual. 64c x 64n, K=64, 256 thr.
// ---------------------------------------------------------------------------
__global__ __launch_bounds__(256) void out_kernel(
    const float* __restrict__ x,
    const float* __restrict__ Wz, const float* __restrict__ bz,
    const float* __restrict__ gamma, const float* __restrict__ beta,
    const float* __restrict__ bn_mean, const float* __restrict__ bn_var,
    float* __restrict__ out)
{
    const int b  = blockIdx.z;
    const int c0 = blockIdx.y * 64;
    const int n0 = blockIdx.x * 64;
    const int tid = threadIdx.x;
    const int tx = tid & 15;   // n quad
    const int ty = tid >> 4;   // c quad

    __shared__ __align__(16) float yS[64][68];
    __shared__ __align__(16) float wzS[64][68];

    const float* yb = d_y + ((size_t)b * NN + n0) * RR;
    for (int i = tid; i < 1024; i += 256) {
        int n = i >> 4, r4 = (i & 15) * 4;
        float4 v = *reinterpret_cast<const float4*>(yb + (size_t)n * RR + r4);
        yS[r4 + 0][n] = v.x; yS[r4 + 1][n] = v.y;
        yS[r4 + 2][n] = v.z; yS[r4 + 3][n] = v.w;
    }
    for (int i = tid; i < 1024; i += 256) {
        int c = i >> 4, r4 = (i & 15) * 4;
        float4 v = *reinterpret_cast<const float4*>(Wz + (size_t)(c0 + c) * RR + r4);
        wzS[r4 + 0][c] = v.x; wzS[r4 + 1][c] = v.y;
        wzS[r4 + 2][c] = v.z; wzS[r4 + 3][c] = v.w;
    }
    __syncthreads();

    u64 acc[4][2];   // [c][n-pair]
#pragma unroll
    for (int i = 0; i < 4; i++) { acc[i][0] = 0ull; acc[i][1] = 0ull; }

#pragma unroll 8
    for (int r = 0; r < 64; r++) {
        float4 cv = *reinterpret_cast<float4*>(&wzS[r][ty * 4]);
        ulonglong2 nv = *reinterpret_cast<ulonglong2*>(&yS[r][tx * 4]);
        u64 cd[4] = {dup2(cv.x), dup2(cv.y), dup2(cv.z), dup2(cv.w)};
#pragma unroll
        for (int i = 0; i < 4; i++) {
            fma2(acc[i][0], cd[i], nv.x);
            fma2(acc[i][1], cd[i], nv.y);
        }
    }

#pragma unroll
    for (int i = 0; i < 4; i++) {
        int c = c0 + ty * 4 + i;
        float a   = rsqrtf(bn_var[c] + EPS) * gamma[c];
        float off = (bz[c] - bn_mean[c]) * a + beta[c];
        size_t base = (size_t)b * CC * NN + (size_t)c * NN + n0 + tx * 4;
        float4 xv = *reinterpret_cast<const float4*>(x + base);
        float2 pa = up2(acc[i][0]), pc = up2(acc[i][1]);
        float4 o;
        o.x = pa.x * a + off + xv.x;
        o.y = pa.y * a + off + xv.y;
        o.z = pc.x * a + off + xv.z;
        o.w = pc.y * a + off + xv.w;
        *reinterpret_cast<float4*>(out + base) = o;
    }
}

// ---------------------------------------------------------------------------
#define ATTN_SMEM (int)((3 * 64 * 68 + 128) * sizeof(float))

extern "C" void kernel_launch(void* const* d_in, const int* in_sizes, int n_in,
                              void* d_out, int out_size)
{
    (void)in_sizes; (void)n_in; (void)out_size;
    const float* x       = (const float*)d_in[0];
    const float* Wt      = (const float*)d_in[1];
    const float* bt      = (const float*)d_in[2];
    const float* Wp      = (const float*)d_in[3];
    const float* bp      = (const float*)d_in[4];
    const float* Wg      = (const float*)d_in[5];
    const float* bg      = (const float*)d_in[6];
    const float* Wz      = (const float*)d_in[7];
    const float* bz      = (const float*)d_in[8];
    const float* gamma   = (const float*)d_in[9];
    const float* beta    = (const float*)d_in[10];
    const float* bn_mean = (const float*)d_in[11];
    const float* bn_var  = (const float*)d_in[12];
    float* out = (float*)d_out;

    cudaFuncSetAttribute(attn_kernel, cudaFuncAttributeMaxDynamicSharedMemorySize, ATTN_SMEM);

    proj_kernel<<<dim3(256, 1, 3), 128>>>(x, Wt, bt, Wp, bp, Wg, bg);
    attn_kernel<<<dim3(16, 32), 256, ATTN_SMEM>>>();
    out_kernel<<<dim3(16, 8, 32), 256>>>(x, Wz, bz, gamma, beta, bn_mean, bn_var, out);
}